// round 16
// baseline (speedup 1.0000x reference)
#include <cuda_runtime.h>
#include <cuda_fp16.h>
#include <cstdint>

#define BATCH 4
#define CIN   256
#define HC    128
#define NPIX  4096

// ---------------- scratch (static __device__, no allocations) ----------------
__device__ __half g_xt_hi[BATCH * NPIX * CIN];  // x^T [b][n][c] hi
__device__ __half g_xt_lo[BATCH * NPIX * CIN];  // x^T lo
__device__ __half g_th_hi[BATCH * NPIX * HC];   // theta [b][n][d] hi
__device__ __half g_ph_hi[BATCH * NPIX * HC];   // phi   [b][m][d] hi
__device__ __half g_gh  [BATCH * HC * NPIX];    // g     [b][d][m] fp16
__device__ __half g_y_hi[BATCH * NPIX * HC];    // y     [b][n][d] hi
__device__ __half g_y_lo[BATCH * NPIX * HC];    // y     [b][n][d] lo

// ---------------- helpers ----------------------------------------------------
__device__ __forceinline__ uint32_t smem_to_u32(const void* p) {
    uint32_t a;
    asm("{ .reg .u64 t; cvta.to.shared.u64 t, %1; cvt.u32.u64 %0, t; }" : "=r"(a) : "l"(p));
    return a;
}

#define LDSM4(r0, r1, r2, r3, addr) \
    asm volatile("ldmatrix.sync.aligned.m8n8.x4.shared.b16 {%0,%1,%2,%3}, [%4];" \
                 : "=r"(r0), "=r"(r1), "=r"(r2), "=r"(r3) : "r"(addr))

#define CP_ASYNC16(dst, src) \
    asm volatile("cp.async.cg.shared.global [%0], [%1], 16;" :: "r"(dst), "l"(src))
#define CP_COMMIT()  asm volatile("cp.async.commit_group;" ::: "memory")
#define CP_WAIT0()   asm volatile("cp.async.wait_group 0;" ::: "memory")

__device__ __forceinline__ void mma16816(float c[4], const uint32_t a[4],
                                         uint32_t b0, uint32_t b1) {
    asm volatile("mma.sync.aligned.m16n8k16.row.col.f32.f16.f16.f32 "
                 "{%0,%1,%2,%3}, {%4,%5,%6,%7}, {%8,%9}, {%0,%1,%2,%3};"
                 : "+f"(c[0]), "+f"(c[1]), "+f"(c[2]), "+f"(c[3])
                 : "r"(a[0]), "r"(a[1]), "r"(a[2]), "r"(a[3]), "r"(b0), "r"(b1));
}

__device__ __forceinline__ uint32_t pack_h2(float lo, float hi) {
    uint32_t u;
    asm("cvt.rn.f16x2.f32 %0, %1, %2;" : "=r"(u) : "f"(hi), "f"(lo));
    return u;
}

// fast exp on the FMA pipe
__device__ __forceinline__ float fexp(float x) {
    float t = x * 1.4426950408889634f;
    t = fminf(fmaxf(t, -125.0f), 125.0f);
    float fi = rintf(t);
    float f  = t - fi;
    float p  = 1.3333558146428443e-3f;
    p = fmaf(p, f, 9.618129107628477e-3f);
    p = fmaf(p, f, 5.550410866482158e-2f);
    p = fmaf(p, f, 2.402265069591007e-1f);
    p = fmaf(p, f, 6.931471805599453e-1f);
    p = fmaf(p, f, 1.0f);
    return __int_as_float(__float_as_int(p) + ((int)fi << 23));
}

// swizzles: 256B rows (16 chunks) and 128B rows (8 chunks)
#define SWZ(r, c)  ((uint32_t)((r) * 256 + (((c) ^ ((r) & 7)) << 4)))
#define SWZP(r, c) ((uint32_t)((r) * 128 + (((c) ^ ((r) & 7)) << 4)))

// ---------------- transpose: x [b][c][n] fp32 -> xT hi/lo [b][n][c] fp16 ------
__global__ __launch_bounds__(256) void xpose_kernel(const float* __restrict__ x)
{
    __shared__ float XS[64][68];
    const int tid = threadIdx.x;
    const int n0 = blockIdx.x * 64;
    const int c0 = blockIdx.y * 64;
    const int b  = blockIdx.z;
    const float* xb = x + ((size_t)b * CIN + c0) * NPIX;
#pragma unroll
    for (int i = 0; i < 4; i++) {
        int c = (tid >> 4) + i * 16;
        int n4 = (tid & 15) * 4;
        float4 v = *(const float4*)&xb[(size_t)c * NPIX + n0 + n4];
        XS[c][n4] = v.x; XS[c][n4 + 1] = v.y; XS[c][n4 + 2] = v.z; XS[c][n4 + 3] = v.w;
    }
    __syncthreads();
    __half* oh = g_xt_hi + ((size_t)b * NPIX + n0) * CIN + c0;
    __half* ol = g_xt_lo + ((size_t)b * NPIX + n0) * CIN + c0;
#pragma unroll
    for (int i = 0; i < 4; i++) {
        int n = (tid >> 4) + i * 16;
        int c4 = (tid & 15) * 4;
        __half h[4], l[4];
#pragma unroll
        for (int q = 0; q < 4; q++) {
            float v = XS[c4 + q][n];
            h[q] = __float2half_rn(v);
            l[q] = __float2half_rn(v - __half2float(h[q]));
        }
        *(uint2*)&oh[(size_t)n * CIN + c4] = *(uint2*)h;
        *(uint2*)&ol[(size_t)n * CIN + c4] = *(uint2*)l;
    }
}

// ---------------- FUSED tensorized projections --------------------------------
// Stages xT once; computes theta (3-chain), phi (3-chain), g (2-chain).
#define P_XH0 0u
#define P_XL0 32768u
#define P_XH1 65536u
#define P_XL1 98304u
#define P_WH  131072u
#define P_WL  163840u
#define P_ZH  131072u          // fp16 ZS [128][136], overlays W region post-mma
#define P_BI  196608u
#define P_SMEM (196608 + 2048)

__global__ __launch_bounds__(256, 1) void proj_fused_kernel(
    const float* __restrict__ w_th, const float* __restrict__ b_th,
    const float* __restrict__ w_ph, const float* __restrict__ b_ph,
    const float* __restrict__ w_g,  const float* __restrict__ b_g)
{
    extern __shared__ char smem[];
    const uint32_t sb = smem_to_u32(smem);
    const int tid = threadIdx.x;
    const int wid = tid >> 5, lane = tid & 31;
    const int wy = wid >> 1;   // n band of 32 (0..3)
    const int wx = wid & 1;    // o half (0..1)
    const int n0 = blockIdx.x * 128;
    const int b  = blockIdx.y;

    const __half* XTH = g_xt_hi + ((size_t)b * NPIX + n0) * CIN;
    const __half* XTL = g_xt_lo + ((size_t)b * NPIX + n0) * CIN;

    // stage A tiles (persist across all three projections)
#pragma unroll
    for (int kc = 0; kc < 2; kc++)
#pragma unroll
        for (int i = 0; i < 8; i++) {
            int id = tid + i * 256;
            int r = id >> 4, c = id & 15;
            CP_ASYNC16(sb + (kc ? P_XH1 : P_XH0) + SWZ(r, c),
                       XTH + (size_t)r * CIN + kc * 128 + c * 8);
            CP_ASYNC16(sb + (kc ? P_XL1 : P_XL0) + SWZ(r, c),
                       XTL + (size_t)r * CIN + kc * 128 + c * 8);
        }
    CP_COMMIT();

    // biases: [which][128]
    if (tid < 128) {
        float* BI = (float*)(smem + P_BI);
        BI[tid]       = b_th[tid];
        BI[128 + tid] = b_ph[tid];
        BI[256 + tid] = b_g[tid];
    }

    const int arow = (lane & 7) + ((lane >> 3) & 1) * 8;
    const int acol = lane >> 4;
    const int brow = (lane & 7) + (lane >> 4) * 8;
    const int bcol = (lane >> 3) & 1;

    const float* wptr[3] = {w_th, w_ph, w_g};
    bool first = true;

#pragma unroll 1
    for (int w_i = 0; w_i < 3; w_i++) {
        const float* w = wptr[w_i];
        const bool lo_chain = (w_i < 2);

        float zacc[2][8][4];
#pragma unroll
        for (int t = 0; t < 2; t++)
#pragma unroll
            for (int j = 0; j < 8; j++)
#pragma unroll
                for (int q = 0; q < 4; q++) zacc[t][j][q] = 0.0f;

#pragma unroll 1
        for (int kc = 0; kc < 2; kc++) {
            __syncthreads();   // prior users of W/ZS region done
            // stage W chunk: fp32 -> fp16 hi (+ lo for theta/phi)
#pragma unroll
            for (int i = 0; i < 16; i++) {
                int id = tid + i * 256;
                int r = id >> 5, q = id & 31;
                float4 v = *(const float4*)&w[(size_t)r * CIN + kc * 128 + q * 4];
                __half h0 = __float2half_rn(v.x), h1 = __float2half_rn(v.y);
                __half h2 = __float2half_rn(v.z), h3 = __float2half_rn(v.w);
                uint32_t ph0 = (uint32_t)*(uint16_t*)&h0 | ((uint32_t)*(uint16_t*)&h1 << 16);
                uint32_t ph1 = (uint32_t)*(uint16_t*)&h2 | ((uint32_t)*(uint16_t*)&h3 << 16);
                uint32_t wa = sb + P_WH + SWZ(r, q >> 1) + (q & 1) * 8;
                asm volatile("st.shared.v2.b32 [%0], {%1,%2};" :: "r"(wa), "r"(ph0), "r"(ph1));
                if (lo_chain) {
                    __half l0 = __float2half_rn(v.x - __half2float(h0));
                    __half l1 = __float2half_rn(v.y - __half2float(h1));
                    __half l2 = __float2half_rn(v.z - __half2float(h2));
                    __half l3 = __float2half_rn(v.w - __half2float(h3));
                    uint32_t pl0 = (uint32_t)*(uint16_t*)&l0 | ((uint32_t)*(uint16_t*)&l1 << 16);
                    uint32_t pl1 = (uint32_t)*(uint16_t*)&l2 | ((uint32_t)*(uint16_t*)&l3 << 16);
                    uint32_t wl = sb + P_WL + SWZ(r, q >> 1) + (q & 1) * 8;
                    asm volatile("st.shared.v2.b32 [%0], {%1,%2};" :: "r"(wl), "r"(pl0), "r"(pl1));
                }
            }
            if (first) { CP_WAIT0(); first = false; }
            __syncthreads();

            const uint32_t xh = sb + (kc ? P_XH1 : P_XH0);
            const uint32_t xl = sb + (kc ? P_XL1 : P_XL0);
#pragma unroll
            for (int kk = 0; kk < 8; kk++) {
                uint32_t ah[2][4], al[2][4];
#pragma unroll
                for (int t = 0; t < 2; t++) {
                    int r = wy * 32 + t * 16 + arow;
                    int c = 2 * kk + acol;
                    LDSM4(ah[t][0], ah[t][1], ah[t][2], ah[t][3], xh + SWZ(r, c));
                    LDSM4(al[t][0], al[t][1], al[t][2], al[t][3], xl + SWZ(r, c));
                }
#pragma unroll
                for (int p = 0; p < 4; p++) {
                    int r = wx * 64 + p * 16 + brow;
                    int c = 2 * kk + bcol;
                    uint32_t bh0, bh1, bh2, bh3;
                    LDSM4(bh0, bh1, bh2, bh3, sb + P_WH + SWZ(r, c));
#pragma unroll
                    for (int t = 0; t < 2; t++) {
                        mma16816(zacc[t][2 * p],     ah[t], bh0, bh1);
                        mma16816(zacc[t][2 * p],     al[t], bh0, bh1);
                        mma16816(zacc[t][2 * p + 1], ah[t], bh2, bh3);
                        mma16816(zacc[t][2 * p + 1], al[t], bh2, bh3);
                    }
                    if (lo_chain) {
                        uint32_t bl0, bl1, bl2, bl3;
                        LDSM4(bl0, bl1, bl2, bl3, sb + P_WL + SWZ(r, c));
#pragma unroll
                        for (int t = 0; t < 2; t++) {
                            mma16816(zacc[t][2 * p],     ah[t], bl0, bl1);
                            mma16816(zacc[t][2 * p + 1], ah[t], bl2, bl3);
                        }
                    }
                }
            }
        }
        __syncthreads();   // all mma LDSM of W done; ZS_h may overwrite W region

        // epilogue: fragments (+bias) -> fp16 ZS_h, then coalesced global store
        __half* ZH = (__half*)(smem + P_ZH);   // [128][136]
        const float* BI = (float*)(smem + P_BI) + w_i * 128;
        if (w_i < 2) {
#pragma unroll
            for (int t = 0; t < 2; t++) {
                int row0 = wy * 32 + t * 16 + (lane >> 2);
#pragma unroll
                for (int j = 0; j < 8; j++) {
                    int col = wx * 64 + j * 8 + (lane & 3) * 2;
                    float b0 = BI[col], b1 = BI[col + 1];
                    *(uint32_t*)&ZH[row0 * 136 + col] =
                        pack_h2(zacc[t][j][0] + b0, zacc[t][j][1] + b1);
                    *(uint32_t*)&ZH[(row0 + 8) * 136 + col] =
                        pack_h2(zacc[t][j][2] + b0, zacc[t][j][3] + b1);
                }
            }
            __syncthreads();
            __half* oh = (w_i == 0 ? g_th_hi : g_ph_hi) + ((size_t)b * NPIX + n0) * HC;
#pragma unroll
            for (int i = 0; i < 8; i++) {
                int id = tid + i * 256;
                int n = id >> 4, d8 = (id & 15) * 8;
                *(uint4*)&oh[(size_t)n * HC + d8] = *(uint4*)&ZH[n * 136 + d8];
            }
        } else {
            // g: transposed staging [o][136 m], output [d][m]
#pragma unroll
            for (int t = 0; t < 2; t++) {
                int row0 = wy * 32 + t * 16 + (lane >> 2);
#pragma unroll
                for (int j = 0; j < 8; j++) {
                    int col = wx * 64 + j * 8 + (lane & 3) * 2;
                    ZH[col * 136 + row0]           = __float2half_rn(zacc[t][j][0] + BI[col]);
                    ZH[(col + 1) * 136 + row0]     = __float2half_rn(zacc[t][j][1] + BI[col + 1]);
                    ZH[col * 136 + row0 + 8]       = __float2half_rn(zacc[t][j][2] + BI[col]);
                    ZH[(col + 1) * 136 + row0 + 8] = __float2half_rn(zacc[t][j][3] + BI[col + 1]);
                }
            }
            __syncthreads();
            __half* ob = g_gh + (size_t)b * HC * NPIX;
#pragma unroll
            for (int i = 0; i < 8; i++) {
                int id = tid + i * 256;
                int d = id >> 4, m8 = (id & 15) * 8;
                *(uint4*)&ob[(size_t)d * NPIX + n0 + m8] = *(uint4*)&ZH[d * 136 + m8];
            }
        }
    }
}

// ---------------- smem layout: 64-row CTA flash -------------------------------
#define TH_OFF  0u
#define PH0H    32768u
#define PH1H    49152u
#define G0_OFF  65536u
#define G1_OFF  81920u
#define PP_OFF  98304u
#define HM_OFF  106496u
#define ES_OFF  106496u
#define OSM_OFF 32768u
#define FLASH_SMEM (107520)

// stage a [64 rows][256B] tile, row stride HC, 128 threads
__device__ __forceinline__ void stage_64_256(uint32_t dst, const __half* __restrict__ src,
                                             int tid) {
#pragma unroll
    for (int i = 0; i < 8; i++) {
        int id = tid + i * 128;
        int r = id >> 4, c = id & 15;
        CP_ASYNC16(dst + SWZ(r, c), src + (size_t)r * HC + c * 8);
    }
}
// stage a [128 rows][128B] tile (g half), row stride NPIX, 128 threads
__device__ __forceinline__ void stage_g_128(uint32_t dst, const __half* __restrict__ src,
                                            int tid) {
#pragma unroll
    for (int i = 0; i < 8; i++) {
        int id = tid + i * 128;
        int r = id >> 3, c = id & 7;
        CP_ASYNC16(dst + SWZP(r, c), src + (size_t)r * NPIX + c * 8);
    }
}

// body macro: H = half index (0..63), PAR = H&1 (literal), SW write sacc, SR read sacc
#define FLASH_BODY(H, PAR, SW, SR) do {                                        \
    if ((H) + 1 < 64) {                                                        \
        const __half* ps = PhH + (size_t)((H) + 1) * 64 * HC;                  \
        stage_64_256(sb + ((PAR) ? PH0H : PH1H), ps, tid);                     \
    }                                                                          \
    stage_g_128(sb + ((PAR) ? G1_OFF : G0_OFF), Gm + (size_t)(H) * 64, tid);   \
    CP_COMMIT();                                                               \
    {   /* step1: MMA1(H) = theta_hi * phi_hi, interleaved epi(H-1) */         \
        _Pragma("unroll")                                                      \
        for (int tz = 0; tz < 2; tz++)                                         \
            _Pragma("unroll")                                                  \
            for (int jz = 0; jz < 4; jz++)                                     \
                _Pragma("unroll")                                              \
                for (int qz = 0; qz < 4; qz++) SW[tz][jz][qz] = 0.0f;          \
        const uint32_t phh = sb + ((PAR) ? PH1H : PH0H);                       \
        _Pragma("unroll")                                                      \
        for (int kk = 0; kk < 8; kk++) {                                       \
            uint32_t ah[2][4];                                                 \
            _Pragma("unroll")                                                  \
            for (int t = 0; t < 2; t++) {                                      \
                int r = wy * 32 + t * 16 + arow;                               \
                int c = 2 * kk + acol;                                         \
                LDSM4(ah[t][0], ah[t][1], ah[t][2], ah[t][3], sb + TH_OFF + SWZ(r, c)); \
            }                                                                  \
            _Pragma("unroll")                                                  \
            for (int p = 0; p < 2; p++) {                                      \
                int r = wx * 32 + p * 16 + brow;                               \
                int c = 2 * kk + bcol;                                         \
                uint32_t bh0, bh1, bh2, bh3;                                   \
                LDSM4(bh0, bh1, bh2, bh3, phh + SWZ(r, c));                    \
                _Pragma("unroll")                                              \
                for (int t = 0; t < 2; t++) {                                  \
                    mma16816(SW[t][2 * p],     ah[t], bh0, bh1);               \
                    mma16816(SW[t][2 * p + 1], ah[t], bh2, bh3);               \
                }                                                              \
            }                                                                  \
            if ((H) > 0) {  /* epi chunk kk: (t,j) = (kk>>2, kk&3) */          \
                const int te = kk >> 2, je = kk & 3;                           \
                float e0 = fexp(SR[te][je][0] - mcur[te * 2]);                 \
                float e1 = fexp(SR[te][je][1] - mcur[te * 2]);                 \
                float e2 = fexp(SR[te][je][2] - mcur[te * 2 + 1]);             \
                float e3 = fexp(SR[te][je][3] - mcur[te * 2 + 1]);             \
                uint32_t p01 = pack_h2(e0, e1);                                \
                uint32_t p23 = pack_h2(e2, e3);                                \
                __half2 h01 = *reinterpret_cast<__half2*>(&p01);               \
                __half2 h23 = *reinterpret_cast<__half2*>(&p23);               \
                esp[te * 2 + 0] += __low2float(h01) + __high2float(h01);       \
                esp[te * 2 + 1] += __low2float(h23) + __high2float(h23);       \
                int row0 = wy * 32 + te * 16 + (lane >> 2);                    \
                int cch  = wx * 4 + je;                                        \
                *(uint32_t*)(smem + PP_OFF + SWZP(row0, cch) + (lane & 3) * 4)     = p01; \
                *(uint32_t*)(smem + PP_OFF + SWZP(row0 + 8, cch) + (lane & 3) * 4) = p23; \
            }                                                                  \
        }                                                                      \
        /* row max of SW -> HM */                                              \
        float mt[4] = {-1e30f, -1e30f, -1e30f, -1e30f};                        \
        _Pragma("unroll")                                                      \
        for (int t = 0; t < 2; t++)                                            \
            _Pragma("unroll")                                                  \
            for (int j = 0; j < 4; j++) {                                      \
                mt[t * 2 + 0] = fmaxf(mt[t * 2 + 0], fmaxf(SW[t][j][0], SW[t][j][1])); \
                mt[t * 2 + 1] = fmaxf(mt[t * 2 + 1], fmaxf(SW[t][j][2], SW[t][j][3])); \
            }                                                                  \
        _Pragma("unroll")                                                      \
        for (int q = 0; q < 4; q++) {                                          \
            mt[q] = fmaxf(mt[q], __shfl_xor_sync(0xFFFFFFFFu, mt[q], 1));      \
            mt[q] = fmaxf(mt[q], __shfl_xor_sync(0xFFFFFFFFu, mt[q], 2));      \
        }                                                                      \
        float* HMp = (float*)(smem + HM_OFF);                                  \
        if ((lane & 3) == 0) {                                                 \
            _Pragma("unroll")                                                  \
            for (int t = 0; t < 2; t++)                                        \
                _Pragma("unroll")                                              \
                for (int h2 = 0; h2 < 2; h2++)                                 \
                    HMp[wx * 64 + wy * 32 + t * 16 + h2 * 8 + (lane >> 2)] = mt[t * 2 + h2]; \
        }                                                                      \
    }                                                                          \
    __syncthreads();                                                           \
    if ((H) > 0) {  /* MMA2(H-1): PP, g of other parity */                     \
        const uint32_t ppb2 = sb + PP_OFF;                                     \
        const uint32_t gb   = sb + ((PAR) ? G0_OFF : G1_OFF);                  \
        _Pragma("unroll")                                                      \
        for (int kk2 = 0; kk2 < 4; kk2++) {                                    \
            uint32_t ap[2][4];                                                 \
            _Pragma("unroll")                                                  \
            for (int t = 0; t < 2; t++) {                                      \
                int r = wy * 32 + t * 16 + arow;                               \
                LDSM4(ap[t][0], ap[t][1], ap[t][2], ap[t][3],                  \
                      ppb2 + SWZP(r, 2 * kk2 + acol));                         \
            }                                                                  \
            _Pragma("unroll")                                                  \
            for (int p = 0; p < 4; p++) {                                      \
                int r = wx * 64 + p * 16 + brow;                               \
                uint32_t bg0, bg1, bg2, bg3;                                   \
                LDSM4(bg0, bg1, bg2, bg3, gb + SWZP(r, 2 * kk2 + bcol));       \
                _Pragma("unroll")                                              \
                for (int t = 0; t < 2; t++) {                                  \
                    mma16816(oacc[t][2 * p],     ap[t], bg0, bg1);             \
                    mma16816(oacc[t][2 * p + 1], ap[t], bg2, bg3);             \
                }                                                              \
            }                                                                  \
        }                                                                      \
    }                                                                          \
    {   /* rescale(H) from HM, lazy */                                         \
        float* HMp = (float*)(smem + HM_OFF);                                  \
        float Mn[4]; int upd = 0;                                              \
        _Pragma("unroll")                                                      \
        for (int t = 0; t < 2; t++)                                            \
            _Pragma("unroll")                                                  \
            for (int h2 = 0; h2 < 2; h2++) {                                   \
                int q = t * 2 + h2;                                            \
                int row = wy * 32 + t * 16 + h2 * 8 + (lane >> 2);             \
                float tm = fmaxf(HMp[row], HMp[64 + row]);                     \
                Mn[q] = fmaxf(mrun[q], tm);                                    \
                upd |= (Mn[q] > mrun[q]);                                      \
            }                                                                  \
        if (__any_sync(0xFFFFFFFFu, upd)) {                                    \
            float scv[4];                                                      \
            _Pragma("unroll")                                                  \
            for (int q = 0; q < 4; q++) {                                      \
                scv[q] = fexp(mrun[q] - Mn[q]);                                \
                mrun[q] = Mn[q]; mcur[q] = Mn[q];                              \
                esp[q] *= scv[q];                                              \
            }                                                                  \
            _Pragma("unroll")                                                  \
            for (int t = 0; t < 2; t++)                                        \
                _Pragma("unroll")                                              \
                for (int j = 0; j < 8; j++) {                                  \
                    oacc[t][j][0] *= scv[t * 2];     oacc[t][j][1] *= scv[t * 2];  \
                    oacc[t][j][2] *= scv[t * 2 + 1]; oacc[t][j][3] *= scv[t * 2 + 1]; \
                }                                                              \
        } else {                                                               \
            _Pragma("unroll")                                                  \
            for (int q = 0; q < 4; q++) mcur[q] = mrun[q];                     \
        }                                                                      \
    }                                                                          \
    CP_WAIT0();                                                                \
    __syncthreads();                                                           \
} while (0)

__global__ __launch_bounds__(128, 2) void flash_mma_kernel()
{
    extern __shared__ char smem[];
    const uint32_t sb = smem_to_u32(smem);
    const int tid  = threadIdx.x;
    const int wid  = tid >> 5, lane = tid & 31;
    const int wy   = wid >> 1;          // n band (0..1)
    const int wx   = wid & 1;           // m / d half (0..1)
    const int n0   = blockIdx.x * 64;
    const int b    = blockIdx.y;

    const __half* ThH = g_th_hi + ((size_t)b * NPIX + n0) * HC;
    const __half* PhH = g_ph_hi + (size_t)b * NPIX * HC;
    const __half* Gm  = g_gh    + (size_t)b * HC * NPIX;
    __half* YbH = g_y_hi + ((size_t)b * NPIX + n0) * HC;
    __half* YbL = g_y_lo + ((size_t)b * NPIX + n0) * HC;

    // prologue: theta hi (resident) + phi(0) hi
    stage_64_256(sb + TH_OFF, ThH, tid);
    stage_64_256(sb + PH0H, PhH, tid);
    CP_COMMIT();
    CP_WAIT0();
    __syncthreads();

    float oacc[2][8][4];
#pragma unroll
    for (int t = 0; t < 2; t++)
#pragma unroll
        for (int j = 0; j < 8; j++)
#pragma unroll
            for (int q = 0; q < 4; q++) oacc[t][j][q] = 0.0f;
    float esp[4]  = {0.0f, 0.0f, 0.0f, 0.0f};
    float mrun[4] = {-1e30f, -1e30f, -1e30f, -1e30f};
    float mcur[4] = {-1e30f, -1e30f, -1e30f, -1e30f};
    float sacc0[2][4][4], sacc1[2][4][4];

    const int arow = (lane & 7) + ((lane >> 3) & 1) * 8;
    const int acol = lane >> 4;
    const int brow = (lane & 7) + (lane >> 4) * 8;
    const int bcol = (lane >> 3) & 1;

#pragma unroll 1
    for (int h = 0; h < 64; h += 2) {
        FLASH_BODY(h,     0, sacc0, sacc1);
        FLASH_BODY(h + 1, 1, sacc1, sacc0);
    }

    // tail body (h = 64): epi(63), barrier, MMA2(63) [g(63) is in G1]
    {
#pragma unroll
        for (int kk = 0; kk < 8; kk++) {
            const int te = kk >> 2, je = kk & 3;
            float e0 = fexp(sacc1[te][je][0] - mcur[te * 2]);
            float e1 = fexp(sacc1[te][je][1] - mcur[te * 2]);
            float e2 = fexp(sacc1[te][je][2] - mcur[te * 2 + 1]);
            float e3 = fexp(sacc1[te][je][3] - mcur[te * 2 + 1]);
            uint32_t p01 = pack_h2(e0, e1);
            uint32_t p23 = pack_h2(e2, e3);
            __half2 h01 = *reinterpret_cast<__half2*>(&p01);
            __half2 h23 = *reinterpret_cast<__half2*>(&p23);
            esp[te * 2 + 0] += __low2float(h01) + __high2float(h01);
            esp[te * 2 + 1] += __low2float(h23) + __high2float(h23);
            int row0 = wy * 32 + te * 16 + (lane >> 2);
            int cch  = wx * 4 + je;
            *(uint32_t*)(smem + PP_OFF + SWZP(row0, cch) + (lane & 3) * 4)     = p01;
            *(uint32_t*)(smem + PP_OFF + SWZP(row0 + 8, cch) + (lane & 3) * 4) = p23;
        }
        __syncthreads();
        const uint32_t ppb2 = sb + PP_OFF;
        const uint32_t gb   = sb + G1_OFF;
#pragma unroll
        for (int kk2 = 0; kk2 < 4; kk2++) {
            uint32_t ap[2][4];
#pragma unroll
            for (int t = 0; t < 2; t++) {
                int r = wy * 32 + t * 16 + arow;
                LDSM4(ap[t][0], ap[t][1], ap[t][2], ap[t][3],
                      ppb2 + SWZP(r, 2 * kk2 + acol));
            }
#pragma unroll
            for (int p = 0; p < 4; p++) {
                int r = wx * 64 + p * 16 + brow;
                uint32_t bg0, bg1, bg2, bg3;
                LDSM4(bg0, bg1, bg2, bg3, gb + SWZP(r, 2 * kk2 + bcol));
#pragma unroll
                for (int t = 0; t < 2; t++) {
                    mma16816(oacc[t][2 * p],     ap[t], bg0, bg1);
                    mma16816(oacc[t][2 * p + 1], ap[t], bg2, bg3);
                }
            }
        }
        __syncthreads();
    }

    // ---- softmax denominators --------------------------------------------
    float* ES = (float*)(smem + ES_OFF);
#pragma unroll
    for (int q = 0; q < 4; q++) {
        float v = esp[q];
        v += __shfl_xor_sync(0xFFFFFFFFu, v, 1);
        v += __shfl_xor_sync(0xFFFFFFFFu, v, 2);
        if ((lane & 3) == 0)
            ES[wx * 64 + wy * 32 + (q >> 1) * 16 + (q & 1) * 8 + (lane >> 2)] = v;
    }
    __syncthreads();

    // ---- normalize, stage O[n][d] in smem --------------------------------
    float* OSM = (float*)(smem + OSM_OFF);   // [64][132]
#pragma unroll
    for (int t = 0; t < 2; t++) {
        int row0 = wy * 32 + t * 16 + (lane >> 2);
        float rv0 = 1.0f / (ES[row0] + ES[64 + row0]);
        float rv1 = 1.0f / (ES[row0 + 8] + ES[64 + row0 + 8]);
#pragma unroll
        for (int j = 0; j < 8; j++) {
            int d = wx * 64 + j * 8 + (lane & 3) * 2;
            OSM[row0 * 132 + d]           = oacc[t][j][0] * rv0;
            OSM[row0 * 132 + d + 1]       = oacc[t][j][1] * rv0;
            OSM[(row0 + 8) * 132 + d]     = oacc[t][j][2] * rv1;
            OSM[(row0 + 8) * 132 + d + 1] = oacc[t][j][3] * rv1;
        }
    }
    __syncthreads();

    // ---- y write as hi/lo fp16 [n][d] (d contiguous) ---------------------
#pragma unroll
    for (int i = 0; i < 8; i++) {
        int id = tid + i * 128;
        int n = id >> 4, d8 = (id & 15) * 8;
        float v[8];
        *(float4*)&v[0] = *(float4*)&OSM[n * 132 + d8];
        *(float4*)&v[4] = *(float4*)&OSM[n * 132 + d8 + 4];
        uint32_t hh[4], ll[4];
#pragma unroll
        for (int q = 0; q < 4; q++) {
            __half h0 = __float2half_rn(v[2 * q]);
            __half h1 = __float2half_rn(v[2 * q + 1]);
            __half l0 = __float2half_rn(v[2 * q]     - __half2float(h0));
            __half l1 = __float2half_rn(v[2 * q + 1] - __half2float(h1));
            hh[q] = (uint32_t)*(uint16_t*)&h0 | ((uint32_t)*(uint16_t*)&h1 << 16);
            ll[q] = (uint32_t)*(uint16_t*)&l0 | ((uint32_t)*(uint16_t*)&l1 << 16);
        }
        *(uint4*)&YbH[(size_t)n * HC + d8] = make_uint4(hh[0], hh[1], hh[2], hh[3]);
        *(uint4*)&YbL[(size_t)n * HC + d8] = make_uint4(ll[0], ll[1], ll[2], ll[3]);
    }
}

// ---------------- tensorized final: z[c][n] = ww[c][d] y[d][n] + b + x --------
#define F_YH 0u
#define F_YL 32768u
#define F_WW 65536u
#define F_ZS 98304u
#define F_SMEM (98304 + 128 * 132 * 4)

__global__ __launch_bounds__(128, 1) void final_tc_kernel(
    const float* __restrict__ ww, const float* __restrict__ bw,
    const float* __restrict__ x, float* __restrict__ out)
{
    extern __shared__ char smem[];
    const uint32_t sb = smem_to_u32(smem);
    const int tid = threadIdx.x;
    const int wid = tid >> 5, lane = tid & 31;
    const int wy = wid >> 1;
    const int wx = wid & 1;
    const int n0 = blockIdx.x * 128;
    const int c0 = blockIdx.y * 128;
    const int b  = blockIdx.z;

    const __half* YH = g_y_hi + ((size_t)b * NPIX + n0) * HC;
    const __half* YL = g_y_lo + ((size_t)b * NPIX + n0) * HC;

#pragma unroll
    for (int i = 0; i < 16; i++) {
        int id = tid + i * 128;
        int r = id >> 4, c = id & 15;
        CP_ASYNC16(sb + F_YH + SWZ(r, c), YH + (size_t)r * HC + c * 8);
        CP_ASYNC16(sb + F_YL + SWZ(r, c), YL + (size_t)r * HC + c * 8);
    }
    CP_COMMIT();

#pragma unroll
    for (int i = 0; i < 32; i++) {
        int id = tid + i * 128;
        int r = id >> 5, q = id & 31;
        float4 v = *(const float4*)&ww[(size_t)(c0 + r) * HC + q * 4];
        uint32_t p0 = pack_h2(v.x, v.y);
        uint32_t p1 = pack_h2(v.z, v.w);
        uint32_t addr = sb + F_WW + SWZ(r, q >> 1) + (q & 1) * 8;
        asm volatile("st.shared.v2.b32 [%0], {%1, %2};" :: "r"(addr), "r"(p0), "r"(p1));
    }
    CP_WAIT0();
    __syncthreads();

    const int arow = (lane & 7) + ((lane >> 3) & 1) * 8;
    const int acol = lane >> 4;
    const int brow = (lane & 7) + (lane >> 4) * 8;
    const int bcol = (lane >> 3) & 1;

    float zacc[4][8][4];
#pragma unroll
    for (int t = 0; t < 4; t++)
#pragma unroll
        for (int j = 0; j < 8; j++)
#pragma unroll
            for (int q = 0; q < 4; q++) zacc[t][j][q] = 0.0f;

#pragma unroll
    for (int kk = 0; kk < 8; kk++) {
        uint32_t ah[4][4], al[4][4];
#pragma unroll
        for (int t = 0; t < 4; t++) {
            int r = wy * 64 + t * 16 + arow;
            int c = 2 * kk + acol;
            LDSM4(ah[t][0], ah[t][1], ah[t][2], ah[t][3], sb + F_YH + SWZ(r, c));
            LDSM4(al[t][0], al[t][1], al[t][2], al[t][3], sb + F_YL + SWZ(r, c));
        }
#pragma unroll
        for (int p = 0; p < 4; p++) {
            int r = wx * 64 + p * 16 + brow;
            int c = 2 * kk + bcol;
            uint32_t b0, b1, b2, b3;
            LDSM4(b0, b1, b2, b3, sb + F_WW + SWZ(r, c));
#pragma unroll
            for (int t = 0; t < 4; t++) {
                mma16816(zacc[t][2 * p],     ah[t], b0, b1);
                mma16816(zacc[t][2 * p],     al[t], b0, b1);
                mma16816(zacc[t][2 * p + 1], ah[t], b2, b3);
                mma16816(zacc[t][2 * p + 1], al[t], b2, b3);
            }
        }
    }
    __syncthreads();

    float* ZS = (float*)(smem + F_ZS);
#pragma unroll
    for (int t = 0; t < 4; t++) {
        int row0 = wy * 64 + t * 16 + (lane >> 2);
#pragma unroll
        for (int j = 0; j < 8; j++) {
            int c = wx * 64 + j * 8 + (lane & 3) * 2;
            ZS[c * 132 + row0]           = zacc[t][j][0];
            ZS[(c + 1) * 132 + row0]     = zacc[t][j][1];
            ZS[c * 132 + row0 + 8]       = zacc[t][j][2];
            ZS[(c + 1) * 132 + row0 + 8] = zacc[t][j][3];
        }
    }
    __syncthreads();

    const float* xb = x + ((size_t)b * CIN + c0) * NPIX;
    float* ob = out + ((size_t)b * CIN + c0) * NPIX;
#pragma unroll
    for (int i = 0; i < 32; i++) {
        int id = tid + i * 128;
        int c = id >> 5, nq = (id & 31) * 4;
        float bi = bw[c0 + c];
        float4 zv = *(float4*)&ZS[c * 132 + nq];
        float4 xv = *(const float4*)&xb[(size_t)c * NPIX + n0 + nq];
        float4 v;
        v.x = zv.x + bi + xv.x; v.y = zv.y + bi + xv.y;
        v.z = zv.z + bi + xv.z; v.w = zv.w + bi + xv.w;
        *(float4*)&ob[(size_t)c * NPIX + n0 + nq] = v;
    }
}

// ---------------- launch -----------------------------------------------------
extern "C" void kernel_launch(void* const* d_in, const int* in_sizes, int n_in,
                              void* d_out, int out_size)
{
    const float* x       = (const float*)d_in[0];
    const float* w_theta = (const float*)d_in[1];
    const float* b_theta = (const float*)d_in[2];
    const float* w_phi   = (const float*)d_in[3];
    const float* b_phi   = (const float*)d_in[4];
    const float* w_g     = (const float*)d_in[5];
    const float* b_g     = (const float*)d_in[6];
    const float* w_w     = (const float*)d_in[7];
    const float* b_w     = (const float*)d_in[8];
    float* out = (float*)d_out;

    cudaFuncSetAttribute(proj_fused_kernel,
                         cudaFuncAttributeMaxDynamicSharedMemorySize, P_SMEM);
    cudaFuncSetAttribute(flash_mma_kernel,
                         cudaFuncAttributeMaxDynamicSharedMemorySize, FLASH_SMEM);
    cudaFuncSetAttribute(final_tc_kernel,
                         cudaFuncAttributeMaxDynamicSharedMemorySize, F_SMEM);

    xpose_kernel<<<dim3(64, 4, BATCH), 256>>>(x);
    proj_fused_kernel<<<dim3(32, BATCH), 256, P_SMEM>>>(
        w_theta, b_theta, w_phi, b_phi, w_g, b_g);
    flash_mma_kernel<<<dim3(64, BATCH), 128, FLASH_SMEM>>>();
    final_tc_kernel<<<dim3(32, 2, BATCH), 128, F_SMEM>>>(w_w, b_w, x, out);
}

// round 17
// speedup vs baseline: 1.1298x; 1.1298x over previous
#include <cuda_runtime.h>
#include <cuda_fp16.h>
#include <cstdint>

#define BATCH 4
#define CIN   256
#define HC    128
#define NPIX  4096

// ---------------- scratch (static __device__, no allocations) ----------------
__device__ __half g_xt_hi[BATCH * NPIX * CIN];  // x^T [b][n][c] hi
__device__ __half g_xt_lo[BATCH * NPIX * CIN];  // x^T lo
__device__ __half g_th_hi[BATCH * NPIX * HC];   // theta [b][n][d] hi
__device__ __half g_ph_hi[BATCH * NPIX * HC];   // phi   [b][m][d] hi
__device__ __half g_gh  [BATCH * HC * NPIX];    // g     [b][d][m] fp16
__device__ __half g_y_hi[BATCH * NPIX * HC];    // y     [b][n][d] hi

// ---------------- helpers ----------------------------------------------------
__device__ __forceinline__ uint32_t smem_to_u32(const void* p) {
    uint32_t a;
    asm("{ .reg .u64 t; cvta.to.shared.u64 t, %1; cvt.u32.u64 %0, t; }" : "=r"(a) : "l"(p));
    return a;
}

#define LDSM4(r0, r1, r2, r3, addr) \
    asm volatile("ldmatrix.sync.aligned.m8n8.x4.shared.b16 {%0,%1,%2,%3}, [%4];" \
                 : "=r"(r0), "=r"(r1), "=r"(r2), "=r"(r3) : "r"(addr))

#define CP_ASYNC16(dst, src) \
    asm volatile("cp.async.cg.shared.global [%0], [%1], 16;" :: "r"(dst), "l"(src))
#define CP_COMMIT()  asm volatile("cp.async.commit_group;" ::: "memory")
#define CP_WAIT0()   asm volatile("cp.async.wait_group 0;" ::: "memory")

__device__ __forceinline__ void mma16816(float c[4], const uint32_t a[4],
                                         uint32_t b0, uint32_t b1) {
    asm volatile("mma.sync.aligned.m16n8k16.row.col.f32.f16.f16.f32 "
                 "{%0,%1,%2,%3}, {%4,%5,%6,%7}, {%8,%9}, {%0,%1,%2,%3};"
                 : "+f"(c[0]), "+f"(c[1]), "+f"(c[2]), "+f"(c[3])
                 : "r"(a[0]), "r"(a[1]), "r"(a[2]), "r"(a[3]), "r"(b0), "r"(b1));
}

__device__ __forceinline__ uint32_t pack_h2(float lo, float hi) {
    uint32_t u;
    asm("cvt.rn.f16x2.f32 %0, %1, %2;" : "=r"(u) : "f"(hi), "f"(lo));
    return u;
}

// fast exp on the FMA pipe
__device__ __forceinline__ float fexp(float x) {
    float t = x * 1.4426950408889634f;
    t = fminf(fmaxf(t, -125.0f), 125.0f);
    float fi = rintf(t);
    float f  = t - fi;
    float p  = 1.3333558146428443e-3f;
    p = fmaf(p, f, 9.618129107628477e-3f);
    p = fmaf(p, f, 5.550410866482158e-2f);
    p = fmaf(p, f, 2.402265069591007e-1f);
    p = fmaf(p, f, 6.931471805599453e-1f);
    p = fmaf(p, f, 1.0f);
    return __int_as_float(__float_as_int(p) + ((int)fi << 23));
}

// swizzles: 256B rows (16 chunks) and 128B rows (8 chunks)
#define SWZ(r, c)  ((uint32_t)((r) * 256 + (((c) ^ ((r) & 7)) << 4)))
#define SWZP(r, c) ((uint32_t)((r) * 128 + (((c) ^ ((r) & 7)) << 4)))

// ---------------- transpose: x [b][c][n] fp32 -> xT hi/lo [b][n][c] fp16 ------
__global__ __launch_bounds__(256) void xpose_kernel(const float* __restrict__ x)
{
    __shared__ float XS[64][68];
    const int tid = threadIdx.x;
    const int n0 = blockIdx.x * 64;
    const int c0 = blockIdx.y * 64;
    const int b  = blockIdx.z;
    const float* xb = x + ((size_t)b * CIN + c0) * NPIX;
#pragma unroll
    for (int i = 0; i < 4; i++) {
        int c = (tid >> 4) + i * 16;
        int n4 = (tid & 15) * 4;
        float4 v = *(const float4*)&xb[(size_t)c * NPIX + n0 + n4];
        XS[c][n4] = v.x; XS[c][n4 + 1] = v.y; XS[c][n4 + 2] = v.z; XS[c][n4 + 3] = v.w;
    }
    __syncthreads();
    __half* oh = g_xt_hi + ((size_t)b * NPIX + n0) * CIN + c0;
    __half* ol = g_xt_lo + ((size_t)b * NPIX + n0) * CIN + c0;
#pragma unroll
    for (int i = 0; i < 4; i++) {
        int n = (tid >> 4) + i * 16;
        int c4 = (tid & 15) * 4;
        __half h[4], l[4];
#pragma unroll
        for (int q = 0; q < 4; q++) {
            float v = XS[c4 + q][n];
            h[q] = __float2half_rn(v);
            l[q] = __float2half_rn(v - __half2float(h[q]));
        }
        *(uint2*)&oh[(size_t)n * CIN + c4] = *(uint2*)h;
        *(uint2*)&ol[(size_t)n * CIN + c4] = *(uint2*)l;
    }
}

// ---------------- tensorized projection ---------------------------------------
// out[n][o] = sum_c xT[n][c] w[o][c] + bias[o]
// which: 0 theta (3-chain), 1 phi (3-chain), 2 g (1-chain, [d][m] out)
#define P_XH0 0u
#define P_XL0 32768u
#define P_XH1 65536u
#define P_XL1 98304u
#define P_WH  131072u
#define P_WL  163840u
#define P_BI  196608u
#define P_SMEM (196608 + 640)

__global__ __launch_bounds__(256, 1) void proj_tc_kernel(
    const float* __restrict__ w, const float* __restrict__ bias, int which)
{
    extern __shared__ char smem[];
    const uint32_t sb = smem_to_u32(smem);
    const int tid = threadIdx.x;
    const int wid = tid >> 5, lane = tid & 31;
    const int wy = wid >> 1;   // n band of 32 (0..3)
    const int wx = wid & 1;    // o half (0..1)
    const int n0 = blockIdx.x * 128;
    const int b  = blockIdx.y;

    const __half* XTH = g_xt_hi + ((size_t)b * NPIX + n0) * CIN;
    const __half* XTL = g_xt_lo + ((size_t)b * NPIX + n0) * CIN;
    const bool lo_chain = (which < 2);

    // stage A tiles, both K chunks: [128 n][128 c] (hi always, lo for theta/phi)
#pragma unroll
    for (int kc = 0; kc < 2; kc++)
#pragma unroll
        for (int i = 0; i < 8; i++) {
            int id = tid + i * 256;
            int r = id >> 4, c = id & 15;
            CP_ASYNC16(sb + (kc ? P_XH1 : P_XH0) + SWZ(r, c),
                       XTH + (size_t)r * CIN + kc * 128 + c * 8);
            if (lo_chain)
                CP_ASYNC16(sb + (kc ? P_XL1 : P_XL0) + SWZ(r, c),
                           XTL + (size_t)r * CIN + kc * 128 + c * 8);
        }
    CP_COMMIT();

    if (tid < 128) ((float*)(smem + P_BI))[tid] = bias[tid];

    const int arow = (lane & 7) + ((lane >> 3) & 1) * 8;
    const int acol = lane >> 4;
    const int brow = (lane & 7) + (lane >> 4) * 8;
    const int bcol = (lane >> 3) & 1;

    float zacc[2][8][4];
#pragma unroll
    for (int t = 0; t < 2; t++)
#pragma unroll
        for (int j = 0; j < 8; j++)
#pragma unroll
            for (int q = 0; q < 4; q++) zacc[t][j][q] = 0.0f;

#pragma unroll 1
    for (int kc = 0; kc < 2; kc++) {
        // stage W chunk: fp32 -> fp16 hi (and lo for theta/phi)
#pragma unroll
        for (int i = 0; i < 16; i++) {
            int id = tid + i * 256;
            int r = id >> 5, q = id & 31;
            float4 v = *(const float4*)&w[(size_t)r * CIN + kc * 128 + q * 4];
            __half h0 = __float2half_rn(v.x), h1 = __float2half_rn(v.y);
            __half h2 = __float2half_rn(v.z), h3 = __float2half_rn(v.w);
            uint32_t ph0 = (uint32_t)*(uint16_t*)&h0 | ((uint32_t)*(uint16_t*)&h1 << 16);
            uint32_t ph1 = (uint32_t)*(uint16_t*)&h2 | ((uint32_t)*(uint16_t*)&h3 << 16);
            uint32_t wa = sb + P_WH + SWZ(r, q >> 1) + (q & 1) * 8;
            asm volatile("st.shared.v2.b32 [%0], {%1,%2};" :: "r"(wa), "r"(ph0), "r"(ph1));
            if (lo_chain) {
                __half l0 = __float2half_rn(v.x - __half2float(h0));
                __half l1 = __float2half_rn(v.y - __half2float(h1));
                __half l2 = __float2half_rn(v.z - __half2float(h2));
                __half l3 = __float2half_rn(v.w - __half2float(h3));
                uint32_t pl0 = (uint32_t)*(uint16_t*)&l0 | ((uint32_t)*(uint16_t*)&l1 << 16);
                uint32_t pl1 = (uint32_t)*(uint16_t*)&l2 | ((uint32_t)*(uint16_t*)&l3 << 16);
                uint32_t wl = sb + P_WL + SWZ(r, q >> 1) + (q & 1) * 8;
                asm volatile("st.shared.v2.b32 [%0], {%1,%2};" :: "r"(wl), "r"(pl0), "r"(pl1));
            }
        }
        if (kc == 0) CP_WAIT0();
        __syncthreads();

        const uint32_t xh = sb + (kc ? P_XH1 : P_XH0);
        const uint32_t xl = sb + (kc ? P_XL1 : P_XL0);
#pragma unroll
        for (int kk = 0; kk < 8; kk++) {
            uint32_t ah[2][4], al[2][4];
#pragma unroll
            for (int t = 0; t < 2; t++) {
                int r = wy * 32 + t * 16 + arow;
                int c = 2 * kk + acol;
                LDSM4(ah[t][0], ah[t][1], ah[t][2], ah[t][3], xh + SWZ(r, c));
                if (lo_chain)
                    LDSM4(al[t][0], al[t][1], al[t][2], al[t][3], xl + SWZ(r, c));
            }
#pragma unroll
            for (int p = 0; p < 4; p++) {
                int r = wx * 64 + p * 16 + brow;
                int c = 2 * kk + bcol;
                uint32_t bh0, bh1, bh2, bh3;
                LDSM4(bh0, bh1, bh2, bh3, sb + P_WH + SWZ(r, c));
#pragma unroll
                for (int t = 0; t < 2; t++) {
                    mma16816(zacc[t][2 * p],     ah[t], bh0, bh1);
                    mma16816(zacc[t][2 * p + 1], ah[t], bh2, bh3);
                }
                if (lo_chain) {
                    uint32_t bl0, bl1, bl2, bl3;
                    LDSM4(bl0, bl1, bl2, bl3, sb + P_WL + SWZ(r, c));
#pragma unroll
                    for (int t = 0; t < 2; t++) {
                        mma16816(zacc[t][2 * p],     al[t], bh0, bh1);
                        mma16816(zacc[t][2 * p + 1], al[t], bh2, bh3);
                        mma16816(zacc[t][2 * p],     ah[t], bl0, bl1);
                        mma16816(zacc[t][2 * p + 1], ah[t], bl2, bl3);
                    }
                }
            }
        }
        __syncthreads();
    }

    // epilogue: stage through ZS (reuses A region — all LDSM complete)
    float* BI = (float*)(smem + P_BI);
    float* ZS = (float*)smem;   // [128][132]
    if (which < 2) {
#pragma unroll
        for (int t = 0; t < 2; t++) {
            int row0 = wy * 32 + t * 16 + (lane >> 2);
#pragma unroll
            for (int j = 0; j < 8; j++) {
                int col = wx * 64 + j * 8 + (lane & 3) * 2;
                float b0 = BI[col], b1 = BI[col + 1];
                ZS[row0 * 132 + col]           = zacc[t][j][0] + b0;
                ZS[row0 * 132 + col + 1]       = zacc[t][j][1] + b1;
                ZS[(row0 + 8) * 132 + col]     = zacc[t][j][2] + b0;
                ZS[(row0 + 8) * 132 + col + 1] = zacc[t][j][3] + b1;
            }
        }
        __syncthreads();
        __half* oh = (which == 0 ? g_th_hi : g_ph_hi) + ((size_t)b * NPIX + n0) * HC;
#pragma unroll
        for (int i = 0; i < 8; i++) {
            int id = tid + i * 256;
            int n = id >> 4, d8 = (id & 15) * 8;
            float v[8];
            *(float4*)&v[0] = *(float4*)&ZS[n * 132 + d8];
            *(float4*)&v[4] = *(float4*)&ZS[n * 132 + d8 + 4];
            __half hs[8];
#pragma unroll
            for (int q = 0; q < 8; q++) hs[q] = __float2half_rn(v[q]);
            *(uint4*)&oh[(size_t)n * HC + d8] = *(uint4*)hs;
        }
    } else {
        // g: transposed staging [o][132 m], output [d][m]
#pragma unroll
        for (int t = 0; t < 2; t++) {
            int row0 = wy * 32 + t * 16 + (lane >> 2);
#pragma unroll
            for (int j = 0; j < 8; j++) {
                int col = wx * 64 + j * 8 + (lane & 3) * 2;
                ZS[col * 132 + row0]           = zacc[t][j][0] + BI[col];
                ZS[(col + 1) * 132 + row0]     = zacc[t][j][1] + BI[col + 1];
                ZS[col * 132 + row0 + 8]       = zacc[t][j][2] + BI[col];
                ZS[(col + 1) * 132 + row0 + 8] = zacc[t][j][3] + BI[col + 1];
            }
        }
        __syncthreads();
        __half* ob = g_gh + (size_t)b * HC * NPIX;
#pragma unroll
        for (int i = 0; i < 8; i++) {
            int id = tid + i * 256;
            int d = id >> 4, m8 = (id & 15) * 8;
            float v[8];
            *(float4*)&v[0] = *(float4*)&ZS[d * 132 + m8];
            *(float4*)&v[4] = *(float4*)&ZS[d * 132 + m8 + 4];
            __half hv[8];
#pragma unroll
            for (int q = 0; q < 8; q++) hv[q] = __float2half_rn(v[q]);
            *(uint4*)&ob[(size_t)d * NPIX + n0 + m8] = *(uint4*)hv;
        }
    }
}

// ---------------- smem layout: 64-row CTA flash -------------------------------
#define TH_OFF  0u
#define PH0H    32768u
#define PH1H    49152u
#define G0_OFF  65536u
#define G1_OFF  81920u
#define PP_OFF  98304u
#define HM_OFF  106496u
#define ES_OFF  106496u
#define OSM_OFF 32768u
#define FLASH_SMEM (107520)

// stage a [64 rows][256B] tile, row stride HC, 128 threads
__device__ __forceinline__ void stage_64_256(uint32_t dst, const __half* __restrict__ src,
                                             int tid) {
#pragma unroll
    for (int i = 0; i < 8; i++) {
        int id = tid + i * 128;
        int r = id >> 4, c = id & 15;
        CP_ASYNC16(dst + SWZ(r, c), src + (size_t)r * HC + c * 8);
    }
}
// stage a [128 rows][128B] tile (g half), row stride NPIX, 128 threads
__device__ __forceinline__ void stage_g_128(uint32_t dst, const __half* __restrict__ src,
                                            int tid) {
#pragma unroll
    for (int i = 0; i < 8; i++) {
        int id = tid + i * 128;
        int r = id >> 3, c = id & 7;
        CP_ASYNC16(dst + SWZP(r, c), src + (size_t)r * NPIX + c * 8);
    }
}

// body macro: H = half index (0..63), PAR = H&1 (literal), SW write sacc, SR read sacc
#define FLASH_BODY(H, PAR, SW, SR) do {                                        \
    if ((H) + 1 < 64) {                                                        \
        const __half* ps = PhH + (size_t)((H) + 1) * 64 * HC;                  \
        stage_64_256(sb + ((PAR) ? PH0H : PH1H), ps, tid);                     \
    }                                                                          \
    stage_g_128(sb + ((PAR) ? G1_OFF : G0_OFF), Gm + (size_t)(H) * 64, tid);   \
    CP_COMMIT();                                                               \
    {   /* step1: MMA1(H) = theta_hi * phi_hi, interleaved epi(H-1) */         \
        _Pragma("unroll")                                                      \
        for (int tz = 0; tz < 2; tz++)                                         \
            _Pragma("unroll")                                                  \
            for (int jz = 0; jz < 4; jz++)                                     \
                _Pragma("unroll")                                              \
                for (int qz = 0; qz < 4; qz++) SW[tz][jz][qz] = 0.0f;          \
        const uint32_t phh = sb + ((PAR) ? PH1H : PH0H);                       \
        _Pragma("unroll")                                                      \
        for (int kk = 0; kk < 8; kk++) {                                       \
            uint32_t ah[2][4];                                                 \
            _Pragma("unroll")                                                  \
            for (int t = 0; t < 2; t++) {                                      \
                int r = wy * 32 + t * 16 + arow;                               \
                int c = 2 * kk + acol;                                         \
                LDSM4(ah[t][0], ah[t][1], ah[t][2], ah[t][3], sb + TH_OFF + SWZ(r, c)); \
            }                                                                  \
            _Pragma("unroll")                                                  \
            for (int p = 0; p < 2; p++) {                                      \
                int r = wx * 32 + p * 16 + brow;                               \
                int c = 2 * kk + bcol;                                         \
                uint32_t bh0, bh1, bh2, bh3;                                   \
                LDSM4(bh0, bh1, bh2, bh3, phh + SWZ(r, c));                    \
                _Pragma("unroll")                                              \
                for (int t = 0; t < 2; t++) {                                  \
                    mma16816(SW[t][2 * p],     ah[t], bh0, bh1);               \
                    mma16816(SW[t][2 * p + 1], ah[t], bh2, bh3);               \
                }                                                              \
            }                                                                  \
            if ((H) > 0) {  /* epi chunk kk: (t,j) = (kk>>2, kk&3) */          \
                const int te = kk >> 2, je = kk & 3;                           \
                float e0 = fexp(SR[te][je][0] - mcur[te * 2]);                 \
                float e1 = fexp(SR[te][je][1] - mcur[te * 2]);                 \
                float e2 = fexp(SR[te][je][2] - mcur[te * 2 + 1]);             \
                float e3 = fexp(SR[te][je][3] - mcur[te * 2 + 1]);             \
                uint32_t p01 = pack_h2(e0, e1);                                \
                uint32_t p23 = pack_h2(e2, e3);                                \
                __half2 h01 = *reinterpret_cast<__half2*>(&p01);               \
                __half2 h23 = *reinterpret_cast<__half2*>(&p23);               \
                esp[te * 2 + 0] += __low2float(h01) + __high2float(h01);       \
                esp[te * 2 + 1] += __low2float(h23) + __high2float(h23);       \
                int row0 = wy * 32 + te * 16 + (lane >> 2);                    \
                int cch  = wx * 4 + je;                                        \
                *(uint32_t*)(smem + PP_OFF + SWZP(row0, cch) + (lane & 3) * 4)     = p01; \
                *(uint32_t*)(smem + PP_OFF + SWZP(row0 + 8, cch) + (lane & 3) * 4) = p23; \
            }                                                                  \
        }                                                                      \
        /* row max of SW -> HM */                                              \
        float mt[4] = {-1e30f, -1e30f, -1e30f, -1e30f};                        \
        _Pragma("unroll")                                                      \
        for (int t = 0; t < 2; t++)                                            \
            _Pragma("unroll")                                                  \
            for (int j = 0; j < 4; j++) {                                      \
                mt[t * 2 + 0] = fmaxf(mt[t * 2 + 0], fmaxf(SW[t][j][0], SW[t][j][1])); \
                mt[t * 2 + 1] = fmaxf(mt[t * 2 + 1], fmaxf(SW[t][j][2], SW[t][j][3])); \
            }                                                                  \
        _Pragma("unroll")                                                      \
        for (int q = 0; q < 4; q++) {                                          \
            mt[q] = fmaxf(mt[q], __shfl_xor_sync(0xFFFFFFFFu, mt[q], 1));      \
            mt[q] = fmaxf(mt[q], __shfl_xor_sync(0xFFFFFFFFu, mt[q], 2));      \
        }                                                                      \
        float* HMp = (float*)(smem + HM_OFF);                                  \
        if ((lane & 3) == 0) {                                                 \
            _Pragma("unroll")                                                  \
            for (int t = 0; t < 2; t++)                                        \
                _Pragma("unroll")                                              \
                for (int h2 = 0; h2 < 2; h2++)                                 \
                    HMp[wx * 64 + wy * 32 + t * 16 + h2 * 8 + (lane >> 2)] = mt[t * 2 + h2]; \
        }                                                                      \
    }                                                                          \
    __syncthreads();                                                           \
    if ((H) > 0) {  /* MMA2(H-1): PP, g of other parity */                     \
        const uint32_t ppb2 = sb + PP_OFF;                                     \
        const uint32_t gb   = sb + ((PAR) ? G0_OFF : G1_OFF);                  \
        _Pragma("unroll")                                                      \
        for (int kk2 = 0; kk2 < 4; kk2++) {                                    \
            uint32_t ap[2][4];                                                 \
            _Pragma("unroll")                                                  \
            for (int t = 0; t < 2; t++) {                                      \
                int r = wy * 32 + t * 16 + arow;                               \
                LDSM4(ap[t][0], ap[t][1], ap[t][2], ap[t][3],                  \
                      ppb2 + SWZP(r, 2 * kk2 + acol));                         \
            }                                                                  \
            _Pragma("unroll")                                                  \
            for (int p = 0; p < 4; p++) {                                      \
                int r = wx * 64 + p * 16 + brow;                               \
                uint32_t bg0, bg1, bg2, bg3;                                   \
                LDSM4(bg0, bg1, bg2, bg3, gb + SWZP(r, 2 * kk2 + bcol));       \
                _Pragma("unroll")                                              \
                for (int t = 0; t < 2; t++) {                                  \
                    mma16816(oacc[t][2 * p],     ap[t], bg0, bg1);             \
                    mma16816(oacc[t][2 * p + 1], ap[t], bg2, bg3);             \
                }                                                              \
            }                                                                  \
        }                                                                      \
    }                                                                          \
    {   /* rescale(H) from HM, lazy */                                         \
        float* HMp = (float*)(smem + HM_OFF);                                  \
        float Mn[4]; int upd = 0;                                              \
        _Pragma("unroll")                                                      \
        for (int t = 0; t < 2; t++)                                            \
            _Pragma("unroll")                                                  \
            for (int h2 = 0; h2 < 2; h2++) {                                   \
                int q = t * 2 + h2;                                            \
                int row = wy * 32 + t * 16 + h2 * 8 + (lane >> 2);             \
                float tm = fmaxf(HMp[row], HMp[64 + row]);                     \
                Mn[q] = fmaxf(mrun[q], tm);                                    \
                upd |= (Mn[q] > mrun[q]);                                      \
            }                                                                  \
        if (__any_sync(0xFFFFFFFFu, upd)) {                                    \
            float scv[4];                                                      \
            _Pragma("unroll")                                                  \
            for (int q = 0; q < 4; q++) {                                      \
                scv[q] = fexp(mrun[q] - Mn[q]);                                \
                mrun[q] = Mn[q]; mcur[q] = Mn[q];                              \
                esp[q] *= scv[q];                                              \
            }                                                                  \
            _Pragma("unroll")                                                  \
            for (int t = 0; t < 2; t++)                                        \
                _Pragma("unroll")                                              \
                for (int j = 0; j < 8; j++) {                                  \
                    oacc[t][j][0] *= scv[t * 2];     oacc[t][j][1] *= scv[t * 2];  \
                    oacc[t][j][2] *= scv[t * 2 + 1]; oacc[t][j][3] *= scv[t * 2 + 1]; \
                }                                                              \
        } else {                                                               \
            _Pragma("unroll")                                                  \
            for (int q = 0; q < 4; q++) mcur[q] = mrun[q];                     \
        }                                                                      \
    }                                                                          \
    CP_WAIT0();                                                                \
    __syncthreads();                                                           \
} while (0)

__global__ __launch_bounds__(128, 2) void flash_mma_kernel()
{
    extern __shared__ char smem[];
    const uint32_t sb = smem_to_u32(smem);
    const int tid  = threadIdx.x;
    const int wid  = tid >> 5, lane = tid & 31;
    const int wy   = wid >> 1;          // n band (0..1)
    const int wx   = wid & 1;           // m / d half (0..1)
    const int n0   = blockIdx.x * 64;
    const int b    = blockIdx.y;

    const __half* ThH = g_th_hi + ((size_t)b * NPIX + n0) * HC;
    const __half* PhH = g_ph_hi + (size_t)b * NPIX * HC;
    const __half* Gm  = g_gh    + (size_t)b * HC * NPIX;
    __half* YbH = g_y_hi + ((size_t)b * NPIX + n0) * HC;

    // prologue: theta hi (resident) + phi(0) hi
    stage_64_256(sb + TH_OFF, ThH, tid);
    stage_64_256(sb + PH0H, PhH, tid);
    CP_COMMIT();
    CP_WAIT0();
    __syncthreads();

    float oacc[2][8][4];
#pragma unroll
    for (int t = 0; t < 2; t++)
#pragma unroll
        for (int j = 0; j < 8; j++)
#pragma unroll
            for (int q = 0; q < 4; q++) oacc[t][j][q] = 0.0f;
    float esp[4]  = {0.0f, 0.0f, 0.0f, 0.0f};
    float mrun[4] = {-1e30f, -1e30f, -1e30f, -1e30f};
    float mcur[4] = {-1e30f, -1e30f, -1e30f, -1e30f};
    float sacc0[2][4][4], sacc1[2][4][4];

    const int arow = (lane & 7) + ((lane >> 3) & 1) * 8;
    const int acol = lane >> 4;
    const int brow = (lane & 7) + (lane >> 4) * 8;
    const int bcol = (lane >> 3) & 1;

#pragma unroll 1
    for (int h = 0; h < 64; h += 2) {
        FLASH_BODY(h,     0, sacc0, sacc1);
        FLASH_BODY(h + 1, 1, sacc1, sacc0);
    }

    // tail body (h = 64): epi(63), barrier, MMA2(63) [g(63) is in G1]
    {
#pragma unroll
        for (int kk = 0; kk < 8; kk++) {
            const int te = kk >> 2, je = kk & 3;
            float e0 = fexp(sacc1[te][je][0] - mcur[te * 2]);
            float e1 = fexp(sacc1[te][je][1] - mcur[te * 2]);
            float e2 = fexp(sacc1[te][je][2] - mcur[te * 2 + 1]);
            float e3 = fexp(sacc1[te][je][3] - mcur[te * 2 + 1]);
            uint32_t p01 = pack_h2(e0, e1);
            uint32_t p23 = pack_h2(e2, e3);
            __half2 h01 = *reinterpret_cast<__half2*>(&p01);
            __half2 h23 = *reinterpret_cast<__half2*>(&p23);
            esp[te * 2 + 0] += __low2float(h01) + __high2float(h01);
            esp[te * 2 + 1] += __low2float(h23) + __high2float(h23);
            int row0 = wy * 32 + te * 16 + (lane >> 2);
            int cch  = wx * 4 + je;
            *(uint32_t*)(smem + PP_OFF + SWZP(row0, cch) + (lane & 3) * 4)     = p01;
            *(uint32_t*)(smem + PP_OFF + SWZP(row0 + 8, cch) + (lane & 3) * 4) = p23;
        }
        __syncthreads();
        const uint32_t ppb2 = sb + PP_OFF;
        const uint32_t gb   = sb + G1_OFF;
#pragma unroll
        for (int kk2 = 0; kk2 < 4; kk2++) {
            uint32_t ap[2][4];
#pragma unroll
            for (int t = 0; t < 2; t++) {
                int r = wy * 32 + t * 16 + arow;
                LDSM4(ap[t][0], ap[t][1], ap[t][2], ap[t][3],
                      ppb2 + SWZP(r, 2 * kk2 + acol));
            }
#pragma unroll
            for (int p = 0; p < 4; p++) {
                int r = wx * 64 + p * 16 + brow;
                uint32_t bg0, bg1, bg2, bg3;
                LDSM4(bg0, bg1, bg2, bg3, gb + SWZP(r, 2 * kk2 + bcol));
#pragma unroll
                for (int t = 0; t < 2; t++) {
                    mma16816(oacc[t][2 * p],     ap[t], bg0, bg1);
                    mma16816(oacc[t][2 * p + 1], ap[t], bg2, bg3);
                }
            }
        }
        __syncthreads();
    }

    // ---- softmax denominators --------------------------------------------
    float* ES = (float*)(smem + ES_OFF);
#pragma unroll
    for (int q = 0; q < 4; q++) {
        float v = esp[q];
        v += __shfl_xor_sync(0xFFFFFFFFu, v, 1);
        v += __shfl_xor_sync(0xFFFFFFFFu, v, 2);
        if ((lane & 3) == 0)
            ES[wx * 64 + wy * 32 + (q >> 1) * 16 + (q & 1) * 8 + (lane >> 2)] = v;
    }
    __syncthreads();

    // ---- normalize, stage O[n][d] in smem --------------------------------
    float* OSM = (float*)(smem + OSM_OFF);   // [64][132]
#pragma unroll
    for (int t = 0; t < 2; t++) {
        int row0 = wy * 32 + t * 16 + (lane >> 2);
        float rv0 = 1.0f / (ES[row0] + ES[64 + row0]);
        float rv1 = 1.0f / (ES[row0 + 8] + ES[64 + row0 + 8]);
#pragma unroll
        for (int j = 0; j < 8; j++) {
            int d = wx * 64 + j * 8 + (lane & 3) * 2;
            OSM[row0 * 132 + d]           = oacc[t][j][0] * rv0;
            OSM[row0 * 132 + d + 1]       = oacc[t][j][1] * rv0;
            OSM[(row0 + 8) * 132 + d]     = oacc[t][j][2] * rv1;
            OSM[(row0 + 8) * 132 + d + 1] = oacc[t][j][3] * rv1;
        }
    }
    __syncthreads();

    // ---- y write as fp16 [n][d] (d contiguous) ---------------------------
#pragma unroll
    for (int i = 0; i < 8; i++) {
        int id = tid + i * 128;
        int n = id >> 4, d8 = (id & 15) * 8;
        float v[8];
        *(float4*)&v[0] = *(float4*)&OSM[n * 132 + d8];
        *(float4*)&v[4] = *(float4*)&OSM[n * 132 + d8 + 4];
        uint32_t hh[4];
#pragma unroll
        for (int q = 0; q < 4; q++)
            hh[q] = pack_h2(v[2 * q], v[2 * q + 1]);
        *(uint4*)&YbH[(size_t)n * HC + d8] = make_uint4(hh[0], hh[1], hh[2], hh[3]);
    }
}

// ---------------- tensorized final: z[c][n] = ww[c][d] y[d][n] + b + x --------
#define F_YH 0u
#define F_WW 32768u
#define F_ZS 65536u
#define F_SMEM (65536 + 128 * 132 * 4)

__global__ __launch_bounds__(128, 1) void final_tc_kernel(
    const float* __restrict__ ww, const float* __restrict__ bw,
    const float* __restrict__ x, float* __restrict__ out)
{
    extern __shared__ char smem[];
    const uint32_t sb = smem_to_u32(smem);
    const int tid = threadIdx.x;
    const int wid = tid >> 5, lane = tid & 31;
    const int wy = wid >> 1;
    const int wx = wid & 1;
    const int n0 = blockIdx.x * 128;
    const int c0 = blockIdx.y * 128;
    const int b  = blockIdx.z;

    const __half* YH = g_y_hi + ((size_t)b * NPIX + n0) * HC;

#pragma unroll
    for (int i = 0; i < 16; i++) {
        int id = tid + i * 128;
        int r = id >> 4, c = id & 15;
        CP_ASYNC16(sb + F_YH + SWZ(r, c), YH + (size_t)r * HC + c * 8);
    }
    CP_COMMIT();

#pragma unroll
    for (int i = 0; i < 32; i++) {
        int id = tid + i * 128;
        int r = id >> 5, q = id & 31;
        float4 v = *(const float4*)&ww[(size_t)(c0 + r) * HC + q * 4];
        uint32_t p0 = pack_h2(v.x, v.y);
        uint32_t p1 = pack_h2(v.z, v.w);
        uint32_t addr = sb + F_WW + SWZ(r, q >> 1) + (q & 1) * 8;
        asm volatile("st.shared.v2.b32 [%0], {%1, %2};" :: "r"(addr), "r"(p0), "r"(p1));
    }
    CP_WAIT0();
    __syncthreads();

    const int arow = (lane & 7) + ((lane >> 3) & 1) * 8;
    const int acol = lane >> 4;
    const int brow = (lane & 7) + (lane >> 4) * 8;
    const int bcol = (lane >> 3) & 1;

    float zacc[4][8][4];
#pragma unroll
    for (int t = 0; t < 4; t++)
#pragma unroll
        for (int j = 0; j < 8; j++)
#pragma unroll
            for (int q = 0; q < 4; q++) zacc[t][j][q] = 0.0f;

#pragma unroll
    for (int kk = 0; kk < 8; kk++) {
        uint32_t ah[4][4];
#pragma unroll
        for (int t = 0; t < 4; t++) {
            int r = wy * 64 + t * 16 + arow;
            int c = 2 * kk + acol;
            LDSM4(ah[t][0], ah[t][1], ah[t][2], ah[t][3], sb + F_YH + SWZ(r, c));
        }
#pragma unroll
        for (int p = 0; p < 4; p++) {
            int r = wx * 64 + p * 16 + brow;
            int c = 2 * kk + bcol;
            uint32_t b0, b1, b2, b3;
            LDSM4(b0, b1, b2, b3, sb + F_WW + SWZ(r, c));
#pragma unroll
            for (int t = 0; t < 4; t++) {
                mma16816(zacc[t][2 * p],     ah[t], b0, b1);
                mma16816(zacc[t][2 * p + 1], ah[t], b2, b3);
            }
        }
    }
    __syncthreads();

    float* ZS = (float*)(smem + F_ZS);
#pragma unroll
    for (int t = 0; t < 4; t++) {
        int row0 = wy * 64 + t * 16 + (lane >> 2);
#pragma unroll
        for (int j = 0; j < 8; j++) {
            int c = wx * 64 + j * 8 + (lane & 3) * 2;
            ZS[c * 132 + row0]           = zacc[t][j][0];
            ZS[(c + 1) * 132 + row0]     = zacc[t][j][1];
            ZS[c * 132 + row0 + 8]       = zacc[t][j][2];
            ZS[(c + 1) * 132 + row0 + 8] = zacc[t][j][3];
        }
    }
    __syncthreads();

    const float* xb = x + ((size_t)b * CIN + c0) * NPIX;
    float* ob = out + ((size_t)b * CIN + c0) * NPIX;
#pragma unroll
    for (int i = 0; i < 32; i++) {
        int id = tid + i * 128;
        int c = id >> 5, nq = (id & 31) * 4;
        float bi = bw[c0 + c];
        float4 zv = *(float4*)&ZS[c * 132 + nq];
        float4 xv = *(const float4*)&xb[(size_t)c * NPIX + n0 + nq];
        float4 v;
        v.x = zv.x + bi + xv.x; v.y = zv.y + bi + xv.y;
        v.z = zv.z + bi + xv.z; v.w = zv.w + bi + xv.w;
        *(float4*)&ob[(size_t)c * NPIX + n0 + nq] = v;
    }
}

// ---------------- launch -----------------------------------------------------
extern "C" void kernel_launch(void* const* d_in, const int* in_sizes, int n_in,
                              void* d_out, int out_size)
{
    const float* x       = (const float*)d_in[0];
    const float* w_theta = (const float*)d_in[1];
    const float* b_theta = (const float*)d_in[2];
    const float* w_phi   = (const float*)d_in[3];
    const float* b_phi   = (const float*)d_in[4];
    const float* w_g     = (const float*)d_in[5];
    const float* b_g     = (const float*)d_in[6];
    const float* w_w     = (const float*)d_in[7];
    const float* b_w     = (const float*)d_in[8];
    float* out = (float*)d_out;

    cudaFuncSetAttribute(proj_tc_kernel,
                         cudaFuncAttributeMaxDynamicSharedMemorySize, P_SMEM);
    cudaFuncSetAttribute(flash_mma_kernel,
                         cudaFuncAttributeMaxDynamicSharedMemorySize, FLASH_SMEM);
    cudaFuncSetAttribute(final_tc_kernel,
                         cudaFuncAttributeMaxDynamicSharedMemorySize, F_SMEM);

    xpose_kernel<<<dim3(64, 4, BATCH), 256>>>(x);
    dim3 gp(32, BATCH);
    proj_tc_kernel<<<gp, 256, P_SMEM>>>(w_theta, b_theta, 0);
    proj_tc_kernel<<<gp, 256, P_SMEM>>>(w_phi,   b_phi,   1);
    proj_tc_kernel<<<gp, 256, P_SMEM>>>(w_g,     b_g,     2);
    flash_mma_kernel<<<dim3(64, BATCH), 128, FLASH_SMEM>>>();
    final_tc_kernel<<<dim3(32, 2, BATCH), 128, F_SMEM>>>(w_w, b_w, x, out);
}